// round 1
// baseline (speedup 1.0000x reference)
#include <cuda_runtime.h>
#include <math.h>

#define B_    8
#define CIN   64
#define COUT  128
#define C2    256
#define HW    65536
#define NBLK  4096
#define EPSV  1e-5f

// ---------------- scratch (device globals: no allocation allowed) ----------------
__device__ float g1buf[(size_t)NBLK * C2 * 64];   // relu(conv1+b1), pre-BN  [blk][ch][px]
__device__ float g2buf[(size_t)NBLK * C2 * 64];   // relu(conv2+b2), pre-BN  [blk][ch][px]
__device__ float g3buf[(size_t)NBLK * COUT * 64]; // relu(conv3+b3), pre-BN  [blk][ch][px]

__device__ double d_sum0[COUT], d_sq0[COUT];
__device__ double d_sum1[C2],   d_sq1[C2];
__device__ double d_sum2[C2],   d_sq2[C2];
__device__ double d_sum3[COUT], d_sq3[COUT];
__device__ float  d_a0[COUT], d_b0[COUT];
__device__ float  d_a1[C2],   d_b1[C2];
__device__ float  d_a2[C2],   d_b2[C2];
__device__ float  d_a3[COUT], d_b3[COUT];

// ---------------- utility ----------------
__global__ void zero_stats_kernel() {
    int t = threadIdx.x;               // 256 threads
    if (t < COUT) { d_sum0[t] = 0.0; d_sq0[t] = 0.0; d_sum3[t] = 0.0; d_sq3[t] = 0.0; }
    d_sum1[t] = 0.0; d_sq1[t] = 0.0; d_sum2[t] = 0.0; d_sq2[t] = 0.0;
}

__device__ __forceinline__ void block_reduce_2(float s, float s2, double* gsum, double* gsq) {
    __shared__ float rs[256], rq[256];
    int t = threadIdx.x;
    rs[t] = s; rq[t] = s2;
    __syncthreads();
    for (int o = 128; o > 0; o >>= 1) {
        if (t < o) { rs[t] += rs[t + o]; rq[t] += rq[t + o]; }
        __syncthreads();
    }
    if (t == 0) { atomicAdd(gsum, (double)rs[0]); atomicAdd(gsq, (double)rq[0]); }
}

__global__ void finalize_kernel(int stage, const float* __restrict__ gamma,
                                const float* __restrict__ beta, double invN) {
    int t = threadIdx.x;
    const double *sum, *sq; float *a, *bsh; int C;
    if (stage == 0)      { sum = d_sum0; sq = d_sq0; a = d_a0; bsh = d_b0; C = COUT; }
    else if (stage == 1) { sum = d_sum1; sq = d_sq1; a = d_a1; bsh = d_b1; C = C2; }
    else if (stage == 2) { sum = d_sum2; sq = d_sq2; a = d_a2; bsh = d_b2; C = C2; }
    else                 { sum = d_sum3; sq = d_sq3; a = d_a3; bsh = d_b3; C = COUT; }
    if (t < C) {
        double mean = sum[t] * invN;
        double var  = sq[t] * invN - mean * mean;
        float v = fmaxf((float)var, 0.0f);
        float av = gamma[t] * rsqrtf(v + EPSV);
        a[t] = av;
        bsh[t] = beta[t] - av * (float)mean;
    }
}

// ---------------- K1: 1x1 conv 64->128 + relu over full image ----------------
// grid 8192 (8 images x 1024 tiles of 64 px), 256 threads
// smem: xs[64ic][64px] + ws[128oc][65]
#define SMEM_CONVC ((64 * 64 + 128 * 65) * 4)
__global__ __launch_bounds__(256) void convc_kernel(const float* __restrict__ x,
                                                    const float* __restrict__ wc,
                                                    const float* __restrict__ bc,
                                                    float* __restrict__ out) {
    extern __shared__ float sm[];
    float* xs = sm;             // 64*64
    float* ws = sm + 64 * 64;   // 128*65
    int b  = blockIdx.x >> 10;
    int p0 = (blockIdx.x & 1023) << 6;
    int t  = threadIdx.x;

    for (int i = t; i < 128 * 64; i += 256) {
        int oc = i >> 6, ic = i & 63;
        ws[oc * 65 + ic] = wc[i];
    }
    for (int i = t; i < 1024; i += 256) {   // 1024 float4 = 64ic x 64px
        int ic = i >> 4, q = i & 15;
        float4 v = *reinterpret_cast<const float4*>(x + (((size_t)(b * CIN + ic)) << 16) + p0 + q * 4);
        *reinterpret_cast<float4*>(xs + ic * 64 + q * 4) = v;
    }
    __syncthreads();

    int px0 = (t & 7) * 8;
    int oc0 = (t >> 3) * 4;
    float acc[4][8];
    #pragma unroll
    for (int j = 0; j < 4; j++)
        #pragma unroll
        for (int c = 0; c < 8; c++) acc[j][c] = 0.0f;

    for (int ic = 0; ic < 64; ic++) {
        float4 xa = *reinterpret_cast<float4*>(xs + ic * 64 + px0);
        float4 xb = *reinterpret_cast<float4*>(xs + ic * 64 + px0 + 4);
        #pragma unroll
        for (int j = 0; j < 4; j++) {
            float w = ws[(oc0 + j) * 65 + ic];
            acc[j][0] += w * xa.x; acc[j][1] += w * xa.y;
            acc[j][2] += w * xa.z; acc[j][3] += w * xa.w;
            acc[j][4] += w * xb.x; acc[j][5] += w * xb.y;
            acc[j][6] += w * xb.z; acc[j][7] += w * xb.w;
        }
    }
    float* dstb = out + (((size_t)(b * COUT)) << 16) + p0;
    #pragma unroll
    for (int j = 0; j < 4; j++) {
        int oc = oc0 + j;
        float bb = bc[oc];
        float4 o1, o2;
        o1.x = fmaxf(acc[j][0] + bb, 0.f); o1.y = fmaxf(acc[j][1] + bb, 0.f);
        o1.z = fmaxf(acc[j][2] + bb, 0.f); o1.w = fmaxf(acc[j][3] + bb, 0.f);
        o2.x = fmaxf(acc[j][4] + bb, 0.f); o2.y = fmaxf(acc[j][5] + bb, 0.f);
        o2.z = fmaxf(acc[j][6] + bb, 0.f); o2.w = fmaxf(acc[j][7] + bb, 0.f);
        *reinterpret_cast<float4*>(dstb + (((size_t)oc) << 16) + px0)     = o1;
        *reinterpret_cast<float4*>(dstb + (((size_t)oc) << 16) + px0 + 4) = o2;
    }
}

// ---------------- stats over d_out [8][128][65536] ----------------
// grid = 128ch * 64 segments, 256 threads
__global__ __launch_bounds__(256) void stats0_kernel(const float* __restrict__ y) {
    int c   = blockIdx.x & 127;
    int seg = blockIdx.x >> 7;           // 0..63
    int b   = seg >> 3;
    int off = (seg & 7) << 13;           // 8192 px per segment
    const float4* p = reinterpret_cast<const float4*>(y + (((size_t)(b * COUT + c)) << 16) + off);
    float s = 0.f, s2 = 0.f;
    for (int i = threadIdx.x; i < 2048; i += 256) {
        float4 v = p[i];
        s  += v.x + v.y + v.z + v.w;
        s2 += v.x * v.x + v.y * v.y + v.z * v.z + v.w * v.w;
    }
    block_reduce_2(s, s2, &d_sum0[c], &d_sq0[c]);
}

// ---------------- apply BN0 to the whole image ----------------
__global__ __launch_bounds__(256) void bnapply_kernel(float* __restrict__ y) {
    int nth = gridDim.x * blockDim.x;
    int total = (B_ * COUT * HW) / 4;
    for (int i = blockIdx.x * blockDim.x + threadIdx.x; i < total; i += nth) {
        int c = (i >> 14) & 127;
        float4 v = reinterpret_cast<float4*>(y)[i];
        float a = d_a0[c], bb = d_b0[c];
        v.x = a * v.x + bb; v.y = a * v.y + bb;
        v.z = a * v.z + bb; v.w = a * v.w + bb;
        reinterpret_cast<float4*>(y)[i] = v;
    }
}

// ---------------- conv1: gather + 1x1 128->256 + relu ----------------
// grid 8192 (blk*2 + half), 256 threads; smem xs[128][64] + ws[128][129]
#define SMEM_C1 ((128 * 64 + 128 * 129) * 4)
__global__ __launch_bounds__(256) void conv1_kernel(const float* __restrict__ xbn,
                                                    const int* __restrict__ abi,
                                                    const float* __restrict__ w1,
                                                    const float* __restrict__ b1) {
    extern __shared__ float sm[];
    float* xs = sm;              // [128ic][64px]
    float* ws = sm + 128 * 64;   // [128oc][129]
    int blk  = blockIdx.x >> 1;
    int half = blockIdx.x & 1;
    int t    = threadIdx.x;
    int n  = abi[blk * 3 + 0];
    int bi = abi[blk * 3 + 1];
    int bj = abi[blk * 3 + 2];
    const float* src = xbn + (((size_t)(n * COUT)) << 16) + bi * 8 * 256 + bj * 8;

    for (int i = t; i < 2048; i += 256) {   // 2048 float4 = 128ic x 64px
        int ic = i >> 4, q = i & 15;
        int r = q >> 1, c4 = (q & 1) * 4;
        float4 v = *reinterpret_cast<const float4*>(src + (((size_t)ic) << 16) + r * 256 + c4);
        *reinterpret_cast<float4*>(xs + ic * 64 + r * 8 + c4) = v;
    }
    const float* wsrc = w1 + half * 128 * 128;
    for (int i = t; i < 16384; i += 256) {
        int oc = i >> 7, ic = i & 127;
        ws[oc * 129 + ic] = wsrc[i];
    }
    __syncthreads();

    int px0 = (t & 7) * 8;
    int oc0 = (t >> 3) * 4;
    float acc[4][8];
    #pragma unroll
    for (int j = 0; j < 4; j++)
        #pragma unroll
        for (int c = 0; c < 8; c++) acc[j][c] = 0.0f;

    for (int ic = 0; ic < 128; ic++) {
        float4 xa = *reinterpret_cast<float4*>(xs + ic * 64 + px0);
        float4 xb = *reinterpret_cast<float4*>(xs + ic * 64 + px0 + 4);
        #pragma unroll
        for (int j = 0; j < 4; j++) {
            float w = ws[(oc0 + j) * 129 + ic];
            acc[j][0] += w * xa.x; acc[j][1] += w * xa.y;
            acc[j][2] += w * xa.z; acc[j][3] += w * xa.w;
            acc[j][4] += w * xb.x; acc[j][5] += w * xb.y;
            acc[j][6] += w * xb.z; acc[j][7] += w * xb.w;
        }
    }
    float* dst = g1buf + ((size_t)blk * C2 + half * 128) * 64;
    #pragma unroll
    for (int j = 0; j < 4; j++) {
        int ocl = oc0 + j;
        float bb = b1[half * 128 + ocl];
        float4 o1, o2;
        o1.x = fmaxf(acc[j][0] + bb, 0.f); o1.y = fmaxf(acc[j][1] + bb, 0.f);
        o1.z = fmaxf(acc[j][2] + bb, 0.f); o1.w = fmaxf(acc[j][3] + bb, 0.f);
        o2.x = fmaxf(acc[j][4] + bb, 0.f); o2.y = fmaxf(acc[j][5] + bb, 0.f);
        o2.z = fmaxf(acc[j][6] + bb, 0.f); o2.w = fmaxf(acc[j][7] + bb, 0.f);
        *reinterpret_cast<float4*>(dst + ocl * 64 + px0)     = o1;
        *reinterpret_cast<float4*>(dst + ocl * 64 + px0 + 4) = o2;
    }
}

// ---------------- generic stats over [NBLK][C][64] buffer ----------------
__device__ __forceinline__ void stats_body(const float* __restrict__ buf, int C,
                                           double* gsum, double* gsq) {
    int c    = blockIdx.x % C;
    int seg  = blockIdx.x / C;     // 0..31
    int blk0 = seg * 128;
    float s = 0.f, s2 = 0.f;
    for (int i = threadIdx.x; i < 128 * 16; i += 256) {
        int bo = i >> 4, q = i & 15;
        float4 v = *reinterpret_cast<const float4*>(buf + ((size_t)(blk0 + bo) * C + c) * 64 + q * 4);
        s  += v.x + v.y + v.z + v.w;
        s2 += v.x * v.x + v.y * v.y + v.z * v.z + v.w * v.w;
    }
    block_reduce_2(s, s2, &gsum[c], &gsq[c]);
}
__global__ __launch_bounds__(256) void stats_g1_kernel() { stats_body(g1buf, C2,   d_sum1, d_sq1); }
__global__ __launch_bounds__(256) void stats_g2_kernel() { stats_body(g2buf, C2,   d_sum2, d_sq2); }
__global__ __launch_bounds__(256) void stats_g3_kernel() { stats_body(g3buf, COUT, d_sum3, d_sq3); }

// ---------------- conv2: 3x3 256->256 per block, zero pad, BN1 folded into loads ----------------
// grid 16384 (blk*4 + ocquarter), 128 threads
// smem: xs[32ic][10*10] + ws[64oc][289]
#define SMEM_C2K ((32 * 100 + 64 * 289) * 4)
__global__ __launch_bounds__(128) void conv2_kernel(const float* __restrict__ w2,
                                                    const float* __restrict__ b2) {
    extern __shared__ float sm[];
    float* xs = sm;            // [32][100] padded 10x10 tiles
    float* ws = sm + 3200;     // [64][289]
    int blk    = blockIdx.x >> 2;
    int ocbase = (blockIdx.x & 3) * 64;
    int t = threadIdx.x;

    for (int i = t; i < 3200; i += 128) xs[i] = 0.0f;   // zero incl. halo (halo stays 0)

    int r   = t & 7;
    int oc0 = (t >> 3) * 4;    // local oc 0..60
    float acc[4][8];
    #pragma unroll
    for (int j = 0; j < 4; j++)
        #pragma unroll
        for (int c = 0; c < 8; c++) acc[j][c] = 0.0f;

    const float* gsrc = g1buf + (size_t)blk * C2 * 64;

    for (int cc = 0; cc < 8; cc++) {
        __syncthreads();
        // load 32 input channels (BN1 applied), into padded interior
        for (int i = t; i < 512; i += 128) {      // 512 float4 = 32ic x 64px
            int ic = i >> 4, q = i & 15;
            int icg = cc * 32 + ic;
            float4 v = *reinterpret_cast<const float4*>(gsrc + (size_t)icg * 64 + q * 4);
            float a = d_a1[icg], bb = d_b1[icg];
            int rr = q >> 1, c4 = (q & 1) * 4;
            float* row = xs + ic * 100 + (rr + 1) * 10 + c4 + 1;
            row[0] = a * v.x + bb; row[1] = a * v.y + bb;
            row[2] = a * v.z + bb; row[3] = a * v.w + bb;
        }
        // load weights [64oc][32ic][9]
        const float* wsrc = w2 + (size_t)ocbase * C2 * 9 + cc * 32 * 9;
        for (int i = t; i < 18432; i += 128) {
            int oc = i / 288;
            int rem = i - oc * 288;
            ws[oc * 289 + rem] = wsrc[(size_t)oc * C2 * 9 + rem];
        }
        __syncthreads();

        for (int ic = 0; ic < 32; ic++) {
            #pragma unroll
            for (int dr = 0; dr < 3; dr++) {
                float xv[10];
                #pragma unroll
                for (int q = 0; q < 10; q++) xv[q] = xs[ic * 100 + (r + dr) * 10 + q];
                float wv[4][3];
                #pragma unroll
                for (int j = 0; j < 4; j++)
                    #pragma unroll
                    for (int dc = 0; dc < 3; dc++)
                        wv[j][dc] = ws[(oc0 + j) * 289 + ic * 9 + dr * 3 + dc];
                #pragma unroll
                for (int j = 0; j < 4; j++)
                    #pragma unroll
                    for (int c = 0; c < 8; c++)
                        acc[j][c] += wv[j][0] * xv[c] + wv[j][1] * xv[c + 1] + wv[j][2] * xv[c + 2];
            }
        }
    }

    float* dst = g2buf + ((size_t)blk * C2 + ocbase) * 64 + r * 8;
    #pragma unroll
    for (int j = 0; j < 4; j++) {
        int oc = ocbase + oc0 + j;
        float bb = b2[oc];
        float4 o1, o2;
        o1.x = fmaxf(acc[j][0] + bb, 0.f); o1.y = fmaxf(acc[j][1] + bb, 0.f);
        o1.z = fmaxf(acc[j][2] + bb, 0.f); o1.w = fmaxf(acc[j][3] + bb, 0.f);
        o2.x = fmaxf(acc[j][4] + bb, 0.f); o2.y = fmaxf(acc[j][5] + bb, 0.f);
        o2.z = fmaxf(acc[j][6] + bb, 0.f); o2.w = fmaxf(acc[j][7] + bb, 0.f);
        *reinterpret_cast<float4*>(dst + (oc0 + j) * 64)     = o1;
        *reinterpret_cast<float4*>(dst + (oc0 + j) * 64 + 4) = o2;
    }
}

// ---------------- conv3: 1x1 256->128 per block, BN2 folded into loads ----------------
// grid 4096 blocks, 256 threads; smem xs[128][64] + ws[128][129], 2 ic-chunks
#define SMEM_C3 ((128 * 64 + 128 * 129) * 4)
__global__ __launch_bounds__(256) void conv3_kernel(const float* __restrict__ w3,
                                                    const float* __restrict__ b3) {
    extern __shared__ float sm[];
    float* xs = sm;              // [128ic][64px]
    float* ws = sm + 128 * 64;   // [128oc][129]
    int blk = blockIdx.x;
    int t = threadIdx.x;
    int px0 = (t & 7) * 8;
    int oc0 = (t >> 3) * 4;
    float acc[4][8];
    #pragma unroll
    for (int j = 0; j < 4; j++)
        #pragma unroll
        for (int c = 0; c < 8; c++) acc[j][c] = 0.0f;

    const float* gsrc = g2buf + (size_t)blk * C2 * 64;

    for (int cc = 0; cc < 2; cc++) {
        __syncthreads();
        for (int i = t; i < 2048; i += 256) {    // 2048 f4 = 128ic x 64px
            int ic = i >> 4, q = i & 15;
            int icg = cc * 128 + ic;
            float4 v = *reinterpret_cast<const float4*>(gsrc + (size_t)icg * 64 + q * 4);
            float a = d_a2[icg], bb = d_b2[icg];
            v.x = a * v.x + bb; v.y = a * v.y + bb;
            v.z = a * v.z + bb; v.w = a * v.w + bb;
            *reinterpret_cast<float4*>(xs + ic * 64 + q * 4) = v;
        }
        const float* wsrc = w3 + cc * 128;
        for (int i = t; i < 16384; i += 256) {
            int oc = i >> 7, ic = i & 127;
            ws[oc * 129 + ic] = wsrc[(size_t)oc * C2 + ic];
        }
        __syncthreads();

        for (int ic = 0; ic < 128; ic++) {
            float4 xa = *reinterpret_cast<float4*>(xs + ic * 64 + px0);
            float4 xb = *reinterpret_cast<float4*>(xs + ic * 64 + px0 + 4);
            #pragma unroll
            for (int j = 0; j < 4; j++) {
                float w = ws[(oc0 + j) * 129 + ic];
                acc[j][0] += w * xa.x; acc[j][1] += w * xa.y;
                acc[j][2] += w * xa.z; acc[j][3] += w * xa.w;
                acc[j][4] += w * xb.x; acc[j][5] += w * xb.y;
                acc[j][6] += w * xb.z; acc[j][7] += w * xb.w;
            }
        }
    }
    float* dst = g3buf + (size_t)blk * COUT * 64;
    #pragma unroll
    for (int j = 0; j < 4; j++) {
        int oc = oc0 + j;
        float bb = b3[oc];
        float4 o1, o2;
        o1.x = fmaxf(acc[j][0] + bb, 0.f); o1.y = fmaxf(acc[j][1] + bb, 0.f);
        o1.z = fmaxf(acc[j][2] + bb, 0.f); o1.w = fmaxf(acc[j][3] + bb, 0.f);
        o2.x = fmaxf(acc[j][4] + bb, 0.f); o2.y = fmaxf(acc[j][5] + bb, 0.f);
        o2.z = fmaxf(acc[j][6] + bb, 0.f); o2.w = fmaxf(acc[j][7] + bb, 0.f);
        *reinterpret_cast<float4*>(dst + oc * 64 + px0)     = o1;
        *reinterpret_cast<float4*>(dst + oc * 64 + px0 + 4) = o2;
    }
}

// ---------------- scatter: BN3(g3) back into the image ----------------
__global__ __launch_bounds__(256) void scatter_kernel(const int* __restrict__ abi,
                                                      float* __restrict__ out) {
    int blk = blockIdx.x;
    int n  = abi[blk * 3 + 0];
    int bi = abi[blk * 3 + 1];
    int bj = abi[blk * 3 + 2];
    const float* src = g3buf + (size_t)blk * COUT * 64;
    float* dst = out + (((size_t)(n * COUT)) << 16) + bi * 8 * 256 + bj * 8;
    for (int i = threadIdx.x; i < 2048; i += 256) {   // 2048 f4 = 128ch x 64px
        int c = i >> 4, q = i & 15;
        int r = q >> 1, c4 = (q & 1) * 4;
        float4 v = *reinterpret_cast<const float4*>(src + c * 64 + q * 4);
        float a = d_a3[c], bb = d_b3[c];
        v.x = a * v.x + bb; v.y = a * v.y + bb;
        v.z = a * v.z + bb; v.w = a * v.w + bb;
        *reinterpret_cast<float4*>(dst + (((size_t)c) << 16) + r * 256 + c4) = v;
    }
}

// ---------------- launch ----------------
extern "C" void kernel_launch(void* const* d_in, const int* in_sizes, int n_in,
                              void* d_out, int out_size) {
    const float* x    = (const float*)d_in[0];
    const int*   abi  = (const int*)  d_in[1];
    const float* w_c  = (const float*)d_in[2];
    const float* b_c  = (const float*)d_in[3];
    const float* gm_c = (const float*)d_in[4];
    const float* be_c = (const float*)d_in[5];
    const float* w1   = (const float*)d_in[6];
    const float* b1   = (const float*)d_in[7];
    const float* gm1  = (const float*)d_in[8];
    const float* be1  = (const float*)d_in[9];
    const float* w2   = (const float*)d_in[10];
    const float* b2   = (const float*)d_in[11];
    const float* gm2  = (const float*)d_in[12];
    const float* be2  = (const float*)d_in[13];
    const float* w3   = (const float*)d_in[14];
    const float* b3   = (const float*)d_in[15];
    const float* gm3  = (const float*)d_in[16];
    const float* be3  = (const float*)d_in[17];
    float* out = (float*)d_out;

    cudaFuncSetAttribute(convc_kernel, cudaFuncAttributeMaxDynamicSharedMemorySize, SMEM_CONVC);
    cudaFuncSetAttribute(conv1_kernel, cudaFuncAttributeMaxDynamicSharedMemorySize, SMEM_C1);
    cudaFuncSetAttribute(conv2_kernel, cudaFuncAttributeMaxDynamicSharedMemorySize, SMEM_C2K);
    cudaFuncSetAttribute(conv3_kernel, cudaFuncAttributeMaxDynamicSharedMemorySize, SMEM_C3);

    zero_stats_kernel<<<1, 256>>>();

    convc_kernel<<<8192, 256, SMEM_CONVC>>>(x, w_c, b_c, out);
    stats0_kernel<<<128 * 64, 256>>>(out);
    finalize_kernel<<<1, 256>>>(0, gm_c, be_c, 1.0 / 524288.0);
    bnapply_kernel<<<16384, 256>>>(out);

    conv1_kernel<<<8192, 256, SMEM_C1>>>(out, abi, w1, b1);
    stats_g1_kernel<<<256 * 32, 256>>>();
    finalize_kernel<<<1, 256>>>(1, gm1, be1, 1.0 / 262144.0);

    conv2_kernel<<<16384, 128, SMEM_C2K>>>(w2, b2);
    stats_g2_kernel<<<256 * 32, 256>>>();
    finalize_kernel<<<1, 256>>>(2, gm2, be2, 1.0 / 262144.0);

    conv3_kernel<<<4096, 256, SMEM_C3>>>(w3, b3);
    stats_g3_kernel<<<128 * 32, 256>>>();
    finalize_kernel<<<1, 256>>>(3, gm3, be3, 1.0 / 262144.0);

    scatter_kernel<<<4096, 256>>>(abi, out);
}

// round 2
// speedup vs baseline: 1.3963x; 1.3963x over previous
#include <cuda_runtime.h>
#include <math.h>

#define B_    8
#define CIN   64
#define COUT  128
#define C2    256
#define HW    65536
#define NBLK  4096
#define EPSV  1e-5f

// ---------------- scratch (device globals: no allocation allowed) ----------------
__device__ float g1buf[(size_t)NBLK * C2 * 64];   // relu(conv1+b1), pre-BN  [blk][ch][px]
__device__ float g2buf[(size_t)NBLK * C2 * 64];   // relu(conv2+b2), pre-BN  [blk][ch][px]
__device__ float g3buf[(size_t)NBLK * COUT * 64]; // relu(conv3+b3), pre-BN  [blk][ch][px]

__device__ double d_sum0[COUT], d_sq0[COUT];
__device__ double d_sum1[C2],   d_sq1[C2];
__device__ double d_sum2[C2],   d_sq2[C2];
__device__ double d_sum3[COUT], d_sq3[COUT];
__device__ float  d_a0[COUT], d_b0[COUT];
__device__ float  d_a1[C2],   d_b1[C2];
__device__ float  d_a2[C2],   d_b2[C2];
__device__ float  d_a3[COUT], d_b3[COUT];

// ---------------- f32x2 packed-FMA helpers ----------------
__device__ __forceinline__ unsigned long long ffma2(unsigned long long a,
                                                    unsigned long long b,
                                                    unsigned long long c) {
    unsigned long long d;
    asm("fma.rn.f32x2 %0, %1, %2, %3;" : "=l"(d) : "l"(a), "l"(b), "l"(c));
    return d;
}
__device__ __forceinline__ unsigned long long pack2(float lo, float hi) {
    unsigned long long r;
    asm("mov.b64 %0, {%1, %2};" : "=l"(r) : "f"(lo), "f"(hi));
    return r;
}
__device__ __forceinline__ unsigned long long dup2(float w) {
    unsigned long long r;
    asm("mov.b64 %0, {%1, %1};" : "=l"(r) : "f"(w));
    return r;
}
__device__ __forceinline__ float2 unpk(unsigned long long v) {
    float2 r;
    asm("mov.b64 {%0, %1}, %2;" : "=f"(r.x), "=f"(r.y) : "l"(v));
    return r;
}

// ---------------- utility ----------------
__global__ void zero_stats_kernel() {
    int t = threadIdx.x;               // 256 threads
    if (t < COUT) { d_sum0[t] = 0.0; d_sq0[t] = 0.0; d_sum3[t] = 0.0; d_sq3[t] = 0.0; }
    d_sum1[t] = 0.0; d_sq1[t] = 0.0; d_sum2[t] = 0.0; d_sq2[t] = 0.0;
}

__device__ __forceinline__ void block_reduce_2(float s, float s2, double* gsum, double* gsq) {
    __shared__ float rs[256], rq[256];
    int t = threadIdx.x;
    rs[t] = s; rq[t] = s2;
    __syncthreads();
    for (int o = 128; o > 0; o >>= 1) {
        if (t < o) { rs[t] += rs[t + o]; rq[t] += rq[t + o]; }
        __syncthreads();
    }
    if (t == 0) { atomicAdd(gsum, (double)rs[0]); atomicAdd(gsq, (double)rq[0]); }
}

__global__ void finalize_kernel(int stage, const float* __restrict__ gamma,
                                const float* __restrict__ beta, double invN) {
    int t = threadIdx.x;
    const double *sum, *sq; float *a, *bsh; int C;
    if (stage == 0)      { sum = d_sum0; sq = d_sq0; a = d_a0; bsh = d_b0; C = COUT; }
    else if (stage == 1) { sum = d_sum1; sq = d_sq1; a = d_a1; bsh = d_b1; C = C2; }
    else if (stage == 2) { sum = d_sum2; sq = d_sq2; a = d_a2; bsh = d_b2; C = C2; }
    else                 { sum = d_sum3; sq = d_sq3; a = d_a3; bsh = d_b3; C = COUT; }
    if (t < C) {
        double mean = sum[t] * invN;
        double var  = sq[t] * invN - mean * mean;
        float v = fmaxf((float)var, 0.0f);
        float av = gamma[t] * rsqrtf(v + EPSV);
        a[t] = av;
        bsh[t] = beta[t] - av * (float)mean;
    }
}

// ---------------- K1: 1x1 conv 64->128 + relu over full image ----------------
#define SMEM_CONVC ((64 * 64 + 128 * 65) * 4)
__global__ __launch_bounds__(256) void convc_kernel(const float* __restrict__ x,
                                                    const float* __restrict__ wc,
                                                    const float* __restrict__ bc,
                                                    float* __restrict__ out) {
    extern __shared__ float sm[];
    float* xs = sm;             // 64*64
    float* ws = sm + 64 * 64;   // 128*65
    int b  = blockIdx.x >> 10;
    int p0 = (blockIdx.x & 1023) << 6;
    int t  = threadIdx.x;

    for (int i = t; i < 128 * 64; i += 256) {
        int oc = i >> 6, ic = i & 63;
        ws[oc * 65 + ic] = wc[i];
    }
    for (int i = t; i < 1024; i += 256) {   // 1024 float4 = 64ic x 64px
        int ic = i >> 4, q = i & 15;
        float4 v = *reinterpret_cast<const float4*>(x + (((size_t)(b * CIN + ic)) << 16) + p0 + q * 4);
        *reinterpret_cast<float4*>(xs + ic * 64 + q * 4) = v;
    }
    __syncthreads();

    int px0 = (t & 7) * 8;
    int oc0 = (t >> 3) * 4;
    float acc[4][8];
    #pragma unroll
    for (int j = 0; j < 4; j++)
        #pragma unroll
        for (int c = 0; c < 8; c++) acc[j][c] = 0.0f;

    for (int ic = 0; ic < 64; ic++) {
        float4 xa = *reinterpret_cast<float4*>(xs + ic * 64 + px0);
        float4 xb = *reinterpret_cast<float4*>(xs + ic * 64 + px0 + 4);
        #pragma unroll
        for (int j = 0; j < 4; j++) {
            float w = ws[(oc0 + j) * 65 + ic];
            acc[j][0] += w * xa.x; acc[j][1] += w * xa.y;
            acc[j][2] += w * xa.z; acc[j][3] += w * xa.w;
            acc[j][4] += w * xb.x; acc[j][5] += w * xb.y;
            acc[j][6] += w * xb.z; acc[j][7] += w * xb.w;
        }
    }
    float* dstb = out + (((size_t)(b * COUT)) << 16) + p0;
    #pragma unroll
    for (int j = 0; j < 4; j++) {
        int oc = oc0 + j;
        float bb = bc[oc];
        float4 o1, o2;
        o1.x = fmaxf(acc[j][0] + bb, 0.f); o1.y = fmaxf(acc[j][1] + bb, 0.f);
        o1.z = fmaxf(acc[j][2] + bb, 0.f); o1.w = fmaxf(acc[j][3] + bb, 0.f);
        o2.x = fmaxf(acc[j][4] + bb, 0.f); o2.y = fmaxf(acc[j][5] + bb, 0.f);
        o2.z = fmaxf(acc[j][6] + bb, 0.f); o2.w = fmaxf(acc[j][7] + bb, 0.f);
        *reinterpret_cast<float4*>(dstb + (((size_t)oc) << 16) + px0)     = o1;
        *reinterpret_cast<float4*>(dstb + (((size_t)oc) << 16) + px0 + 4) = o2;
    }
}

// ---------------- stats over d_out [8][128][65536] ----------------
__global__ __launch_bounds__(256) void stats0_kernel(const float* __restrict__ y) {
    int c   = blockIdx.x & 127;
    int seg = blockIdx.x >> 7;           // 0..63
    int b   = seg >> 3;
    int off = (seg & 7) << 13;           // 8192 px per segment
    const float4* p = reinterpret_cast<const float4*>(y + (((size_t)(b * COUT + c)) << 16) + off);
    float s = 0.f, s2 = 0.f;
    for (int i = threadIdx.x; i < 2048; i += 256) {
        float4 v = p[i];
        s  += v.x + v.y + v.z + v.w;
        s2 += v.x * v.x + v.y * v.y + v.z * v.z + v.w * v.w;
    }
    block_reduce_2(s, s2, &d_sum0[c], &d_sq0[c]);
}

// ---------------- apply BN0 to the whole image ----------------
__global__ __launch_bounds__(256) void bnapply_kernel(float* __restrict__ y) {
    int nth = gridDim.x * blockDim.x;
    int total = (B_ * COUT * HW) / 4;
    for (int i = blockIdx.x * blockDim.x + threadIdx.x; i < total; i += nth) {
        int c = (i >> 14) & 127;
        float4 v = reinterpret_cast<float4*>(y)[i];
        float a = d_a0[c], bb = d_b0[c];
        v.x = a * v.x + bb; v.y = a * v.y + bb;
        v.z = a * v.z + bb; v.w = a * v.w + bb;
        reinterpret_cast<float4*>(y)[i] = v;
    }
}

// ---------------- conv1: gather + 1x1 128->256 + relu (FFMA2) ----------------
// grid 4096 (1 block, all 256 oc), 256 threads
// smem: xs[128][64] + ws[64 ic][260] transposed [ic][oc]
#define SMEM_C1 ((128 * 64 + 64 * 260) * 4)
__global__ __launch_bounds__(256) void conv1f2_kernel(const float* __restrict__ xbn,
                                                      const int* __restrict__ abi,
                                                      const float* __restrict__ w1,
                                                      const float* __restrict__ b1) {
    extern __shared__ float sm[];
    float* xs = sm;              // [128ic][64px]
    float* ws = sm + 128 * 64;   // [64ic][260] (oc-major rows)
    int blk  = blockIdx.x;
    int t    = threadIdx.x;
    int lane = t & 31;
    int warp = t >> 5;
    int px0  = warp * 8;

    int n  = abi[blk * 3 + 0];
    int bi = abi[blk * 3 + 1];
    int bj = abi[blk * 3 + 2];
    const float* src = xbn + (((size_t)(n * COUT)) << 16) + bi * 8 * 256 + bj * 8;

    for (int i = t; i < 2048; i += 256) {   // 2048 float4 = 128ic x 64px
        int ic = i >> 4, q = i & 15;
        int r = q >> 1, c4 = (q & 1) * 4;
        float4 v = *reinterpret_cast<const float4*>(src + (((size_t)ic) << 16) + r * 256 + c4);
        *reinterpret_cast<float4*>(xs + ic * 64 + r * 8 + c4) = v;
    }

    unsigned long long acc[8][4];
    #pragma unroll
    for (int j = 0; j < 8; j++)
        #pragma unroll
        for (int p = 0; p < 4; p++) acc[j][p] = 0ull;

    for (int cc = 0; cc < 2; cc++) {
        __syncthreads();
        // load + transpose weights: ws[ic][oc], ic in [cc*64, cc*64+64)
        for (int i = t; i < 16384; i += 256) {
            int ic = i & 63, oc = i >> 6;
            ws[ic * 260 + oc] = w1[(size_t)oc * 128 + cc * 64 + ic];
        }
        __syncthreads();

        #pragma unroll 2
        for (int ic = 0; ic < 64; ic++) {
            ulonglong2 xa = *reinterpret_cast<const ulonglong2*>(xs + (cc * 64 + ic) * 64 + px0);
            ulonglong2 xb = *reinterpret_cast<const ulonglong2*>(xs + (cc * 64 + ic) * 64 + px0 + 4);
            float4 wlo = *reinterpret_cast<const float4*>(ws + ic * 260 + lane * 4);
            float4 whi = *reinterpret_cast<const float4*>(ws + ic * 260 + 128 + lane * 4);
            unsigned long long wd[8];
            wd[0] = dup2(wlo.x); wd[1] = dup2(wlo.y); wd[2] = dup2(wlo.z); wd[3] = dup2(wlo.w);
            wd[4] = dup2(whi.x); wd[5] = dup2(whi.y); wd[6] = dup2(whi.z); wd[7] = dup2(whi.w);
            #pragma unroll
            for (int j = 0; j < 8; j++) {
                acc[j][0] = ffma2(xa.x, wd[j], acc[j][0]);
                acc[j][1] = ffma2(xa.y, wd[j], acc[j][1]);
                acc[j][2] = ffma2(xb.x, wd[j], acc[j][2]);
                acc[j][3] = ffma2(xb.y, wd[j], acc[j][3]);
            }
        }
    }

    float* dst = g1buf + (size_t)blk * C2 * 64;
    #pragma unroll
    for (int j = 0; j < 8; j++) {
        int oc = (j < 4) ? (lane * 4 + j) : (128 + lane * 4 + (j - 4));
        float bb = b1[oc];
        float2 p0 = unpk(acc[j][0]), p1 = unpk(acc[j][1]);
        float2 p2 = unpk(acc[j][2]), p3 = unpk(acc[j][3]);
        float4 o1, o2;
        o1.x = fmaxf(p0.x + bb, 0.f); o1.y = fmaxf(p0.y + bb, 0.f);
        o1.z = fmaxf(p1.x + bb, 0.f); o1.w = fmaxf(p1.y + bb, 0.f);
        o2.x = fmaxf(p2.x + bb, 0.f); o2.y = fmaxf(p2.y + bb, 0.f);
        o2.z = fmaxf(p3.x + bb, 0.f); o2.w = fmaxf(p3.y + bb, 0.f);
        *reinterpret_cast<float4*>(dst + oc * 64 + px0)     = o1;
        *reinterpret_cast<float4*>(dst + oc * 64 + px0 + 4) = o2;
    }
}

// ---------------- generic stats over [NBLK][C][64] buffer ----------------
__device__ __forceinline__ void stats_body(const float* __restrict__ buf, int C,
                                           double* gsum, double* gsq) {
    int c    = blockIdx.x % C;
    int seg  = blockIdx.x / C;     // 0..31
    int blk0 = seg * 128;
    float s = 0.f, s2 = 0.f;
    for (int i = threadIdx.x; i < 128 * 16; i += 256) {
        int bo = i >> 4, q = i & 15;
        float4 v = *reinterpret_cast<const float4*>(buf + ((size_t)(blk0 + bo) * C + c) * 64 + q * 4);
        s  += v.x + v.y + v.z + v.w;
        s2 += v.x * v.x + v.y * v.y + v.z * v.z + v.w * v.w;
    }
    block_reduce_2(s, s2, &gsum[c], &gsq[c]);
}
__global__ __launch_bounds__(256) void stats_g1_kernel() { stats_body(g1buf, C2,   d_sum1, d_sq1); }
__global__ __launch_bounds__(256) void stats_g2_kernel() { stats_body(g2buf, C2,   d_sum2, d_sq2); }
__global__ __launch_bounds__(256) void stats_g3_kernel() { stats_body(g3buf, COUT, d_sum3, d_sq3); }

// ---------------- conv2: 3x3 256->256, FFMA2, 2 blocks x 64 oc per CTA ----------------
// grid 8192 = 2048 block-pairs x 4 oc-quarters, 128 threads
// smem: xs[2][32][10 rows x 12] + ws[288][66]  ([ic*9+k][oc] transposed)
#define SMEM_C2K ((2 * 32 * 120 + 288 * 66) * 4)
__global__ __launch_bounds__(128) void conv2f2_kernel(const float* __restrict__ w2,
                                                      const float* __restrict__ b2) {
    extern __shared__ float sm[];
    float* xs = sm;                 // 2 * 3840
    float* ws = sm + 2 * 3840;      // 288 * 66
    int pairidx = blockIdx.x >> 2;
    int ocbase  = (blockIdx.x & 3) << 6;
    int blk0    = pairidx * 2;
    int t   = threadIdx.x;
    int ocg = t & 15;       // 16 oc groups
    int r   = t >> 4;       // 8 rows

    for (int i = t; i < 2 * 3840; i += 128) xs[i] = 0.0f;   // zero incl. halo

    unsigned long long acc[2][4][4];
    #pragma unroll
    for (int bq = 0; bq < 2; bq++)
        #pragma unroll
        for (int j = 0; j < 4; j++)
            #pragma unroll
            for (int p = 0; p < 4; p++) acc[bq][j][p] = 0ull;

    const float* g0 = g1buf + (size_t)blk0 * C2 * 64;

    for (int cc = 0; cc < 8; cc++) {
        __syncthreads();
        // x: 2 blocks x 32 ic, BN1 applied, into padded 10x12 tiles
        for (int i = t; i < 1024; i += 128) {        // 1024 float4
            int bq = i >> 9, ic = (i >> 4) & 31, q = i & 15;
            int icg = cc * 32 + ic;
            float4 v = *reinterpret_cast<const float4*>(g0 + ((size_t)bq * C2 + icg) * 64 + q * 4);
            float a = d_a1[icg], bb = d_b1[icg];
            int rr = q >> 1, c4 = (q & 1) * 4;
            float* row = xs + bq * 3840 + ic * 120 + (rr + 1) * 12 + c4 + 1;
            row[0] = a * v.x + bb; row[1] = a * v.y + bb;
            row[2] = a * v.z + bb; row[3] = a * v.w + bb;
        }
        // weights: [oc 64][ic 32][9] -> ws[(ic*9+k)][oc]
        const float* wsrc = w2 + (size_t)ocbase * C2 * 9 + cc * 288;
        for (int i = t; i < 18432; i += 128) {
            int oc = i / 288;
            int rem = i - oc * 288;
            ws[rem * 66 + oc] = wsrc[(size_t)oc * C2 * 9 + rem];
        }
        __syncthreads();

        #pragma unroll 1
        for (int ic = 0; ic < 32; ic++) {
            const float* wrow = ws + ic * 9 * 66;
            #pragma unroll
            for (int dr = 0; dr < 3; dr++) {
                unsigned long long wp[3][4];
                #pragma unroll
                for (int dc = 0; dc < 3; dc++) {
                    float2 wl = *reinterpret_cast<const float2*>(wrow + (dr * 3 + dc) * 66 + ocg * 2);
                    float2 wh = *reinterpret_cast<const float2*>(wrow + (dr * 3 + dc) * 66 + 32 + ocg * 2);
                    wp[dc][0] = dup2(wl.x); wp[dc][1] = dup2(wl.y);
                    wp[dc][2] = dup2(wh.x); wp[dc][3] = dup2(wh.y);
                }
                #pragma unroll
                for (int bq = 0; bq < 2; bq++) {
                    const float* row = xs + bq * 3840 + ic * 120 + (r + dr) * 12;
                    float4 xa = *reinterpret_cast<const float4*>(row);
                    float4 xb = *reinterpret_cast<const float4*>(row + 4);
                    float2 xc = *reinterpret_cast<const float2*>(row + 8);
                    float xv[10] = {xa.x, xa.y, xa.z, xa.w, xb.x, xb.y, xb.z, xb.w, xc.x, xc.y};
                    #pragma unroll
                    for (int dc = 0; dc < 3; dc++) {
                        #pragma unroll
                        for (int p = 0; p < 4; p++) {
                            unsigned long long xp = pack2(xv[2 * p + dc], xv[2 * p + dc + 1]);
                            acc[bq][0][p] = ffma2(xp, wp[dc][0], acc[bq][0][p]);
                            acc[bq][1][p] = ffma2(xp, wp[dc][1], acc[bq][1][p]);
                            acc[bq][2][p] = ffma2(xp, wp[dc][2], acc[bq][2][p]);
                            acc[bq][3][p] = ffma2(xp, wp[dc][3], acc[bq][3][p]);
                        }
                    }
                }
            }
        }
    }

    #pragma unroll
    for (int bq = 0; bq < 2; bq++) {
        float* dst = g2buf + (size_t)(blk0 + bq) * C2 * 64 + r * 8;
        #pragma unroll
        for (int j = 0; j < 4; j++) {
            int oc = ocbase + ((j < 2) ? (ocg * 2 + j) : (32 + ocg * 2 + (j - 2)));
            float bb = b2[oc];
            float2 p0 = unpk(acc[bq][j][0]), p1 = unpk(acc[bq][j][1]);
            float2 p2 = unpk(acc[bq][j][2]), p3 = unpk(acc[bq][j][3]);
            float4 o1, o2;
            o1.x = fmaxf(p0.x + bb, 0.f); o1.y = fmaxf(p0.y + bb, 0.f);
            o1.z = fmaxf(p1.x + bb, 0.f); o1.w = fmaxf(p1.y + bb, 0.f);
            o2.x = fmaxf(p2.x + bb, 0.f); o2.y = fmaxf(p2.y + bb, 0.f);
            o2.z = fmaxf(p3.x + bb, 0.f); o2.w = fmaxf(p3.y + bb, 0.f);
            *reinterpret_cast<float4*>(dst + oc * 64)     = o1;
            *reinterpret_cast<float4*>(dst + oc * 64 + 4) = o2;
        }
    }
}

// ---------------- conv3: 1x1 256->128, FFMA2, BN2 folded ----------------
// grid 4096, 128 threads; smem xs[128][64] + ws[128][132]
#define SMEM_C3 ((128 * 64 + 128 * 132) * 4)
__global__ __launch_bounds__(128) void conv3f2_kernel(const float* __restrict__ w3,
                                                      const float* __restrict__ b3) {
    extern __shared__ float sm[];
    float* xs = sm;              // [128ic][64px]
    float* ws = sm + 128 * 64;   // [128ic][132]
    int blk = blockIdx.x;
    int t   = threadIdx.x;
    int ocg = t & 15;
    int px0 = (t >> 4) * 8;

    unsigned long long acc[8][4];
    #pragma unroll
    for (int j = 0; j < 8; j++)
        #pragma unroll
        for (int p = 0; p < 4; p++) acc[j][p] = 0ull;

    const float* gsrc = g2buf + (size_t)blk * C2 * 64;

    for (int cc = 0; cc < 2; cc++) {
        __syncthreads();
        for (int i = t; i < 2048; i += 128) {    // 2048 f4 = 128ic x 64px
            int ic = i >> 4, q = i & 15;
            int icg = cc * 128 + ic;
            float4 v = *reinterpret_cast<const float4*>(gsrc + (size_t)icg * 64 + q * 4);
            float a = d_a2[icg], bb = d_b2[icg];
            v.x = a * v.x + bb; v.y = a * v.y + bb;
            v.z = a * v.z + bb; v.w = a * v.w + bb;
            *reinterpret_cast<float4*>(xs + ic * 64 + q * 4) = v;
        }
        for (int i = t; i < 16384; i += 128) {
            int ic = i & 127, oc = i >> 7;
            ws[ic * 132 + oc] = w3[(size_t)oc * C2 + cc * 128 + ic];
        }
        __syncthreads();

        #pragma unroll 2
        for (int ic = 0; ic < 128; ic++) {
            ulonglong2 xa = *reinterpret_cast<const ulonglong2*>(xs + ic * 64 + px0);
            ulonglong2 xb = *reinterpret_cast<const ulonglong2*>(xs + ic * 64 + px0 + 4);
            float4 wlo = *reinterpret_cast<const float4*>(ws + ic * 132 + ocg * 4);
            float4 whi = *reinterpret_cast<const float4*>(ws + ic * 132 + 64 + ocg * 4);
            unsigned long long wd[8];
            wd[0] = dup2(wlo.x); wd[1] = dup2(wlo.y); wd[2] = dup2(wlo.z); wd[3] = dup2(wlo.w);
            wd[4] = dup2(whi.x); wd[5] = dup2(whi.y); wd[6] = dup2(whi.z); wd[7] = dup2(whi.w);
            #pragma unroll
            for (int j = 0; j < 8; j++) {
                acc[j][0] = ffma2(xa.x, wd[j], acc[j][0]);
                acc[j][1] = ffma2(xa.y, wd[j], acc[j][1]);
                acc[j][2] = ffma2(xb.x, wd[j], acc[j][2]);
                acc[j][3] = ffma2(xb.y, wd[j], acc[j][3]);
            }
        }
    }

    float* dst = g3buf + (size_t)blk * COUT * 64;
    #pragma unroll
    for (int j = 0; j < 8; j++) {
        int oc = (j < 4) ? (ocg * 4 + j) : (64 + ocg * 4 + (j - 4));
        float bb = b3[oc];
        float2 p0 = unpk(acc[j][0]), p1 = unpk(acc[j][1]);
        float2 p2 = unpk(acc[j][2]), p3 = unpk(acc[j][3]);
        float4 o1, o2;
        o1.x = fmaxf(p0.x + bb, 0.f); o1.y = fmaxf(p0.y + bb, 0.f);
        o1.z = fmaxf(p1.x + bb, 0.f); o1.w = fmaxf(p1.y + bb, 0.f);
        o2.x = fmaxf(p2.x + bb, 0.f); o2.y = fmaxf(p2.y + bb, 0.f);
        o2.z = fmaxf(p3.x + bb, 0.f); o2.w = fmaxf(p3.y + bb, 0.f);
        *reinterpret_cast<float4*>(dst + oc * 64 + px0)     = o1;
        *reinterpret_cast<float4*>(dst + oc * 64 + px0 + 4) = o2;
    }
}

// ---------------- scatter: BN3(g3) back into the image ----------------
__global__ __launch_bounds__(256) void scatter_kernel(const int* __restrict__ abi,
                                                      float* __restrict__ out) {
    int blk = blockIdx.x;
    int n  = abi[blk * 3 + 0];
    int bi = abi[blk * 3 + 1];
    int bj = abi[blk * 3 + 2];
    const float* src = g3buf + (size_t)blk * COUT * 64;
    float* dst = out + (((size_t)(n * COUT)) << 16) + bi * 8 * 256 + bj * 8;
    for (int i = threadIdx.x; i < 2048; i += 256) {   // 2048 f4 = 128ch x 64px
        int c = i >> 4, q = i & 15;
        int r = q >> 1, c4 = (q & 1) * 4;
        float4 v = *reinterpret_cast<const float4*>(src + c * 64 + q * 4);
        float a = d_a3[c], bb = d_b3[c];
        v.x = a * v.x + bb; v.y = a * v.y + bb;
        v.z = a * v.z + bb; v.w = a * v.w + bb;
        *reinterpret_cast<float4*>(dst + (((size_t)c) << 16) + r * 256 + c4) = v;
    }
}

// ---------------- launch ----------------
extern "C" void kernel_launch(void* const* d_in, const int* in_sizes, int n_in,
                              void* d_out, int out_size) {
    const float* x    = (const float*)d_in[0];
    const int*   abi  = (const int*)  d_in[1];
    const float* w_c  = (const float*)d_in[2];
    const float* b_c  = (const float*)d_in[3];
    const float* gm_c = (const float*)d_in[4];
    const float* be_c = (const float*)d_in[5];
    const float* w1   = (const float*)d_in[6];
    const float* b1   = (const float*)d_in[7];
    const float* gm1  = (const float*)d_in[8];
    const float* be1  = (const float*)d_in[9];
    const float* w2   = (const float*)d_in[10];
    const float* b2   = (const float*)d_in[11];
    const float* gm2  = (const float*)d_in[12];
    const float* be2  = (const float*)d_in[13];
    const float* w3   = (const float*)d_in[14];
    const float* b3   = (const float*)d_in[15];
    const float* gm3  = (const float*)d_in[16];
    const float* be3  = (const float*)d_in[17];
    float* out = (float*)d_out;

    cudaFuncSetAttribute(convc_kernel,   cudaFuncAttributeMaxDynamicSharedMemorySize, SMEM_CONVC);
    cudaFuncSetAttribute(conv1f2_kernel, cudaFuncAttributeMaxDynamicSharedMemorySize, SMEM_C1);
    cudaFuncSetAttribute(conv2f2_kernel, cudaFuncAttributeMaxDynamicSharedMemorySize, SMEM_C2K);
    cudaFuncSetAttribute(conv3f2_kernel, cudaFuncAttributeMaxDynamicSharedMemorySize, SMEM_C3);

    zero_stats_kernel<<<1, 256>>>();

    convc_kernel<<<8192, 256, SMEM_CONVC>>>(x, w_c, b_c, out);
    stats0_kernel<<<128 * 64, 256>>>(out);
    finalize_kernel<<<1, 256>>>(0, gm_c, be_c, 1.0 / 524288.0);
    bnapply_kernel<<<16384, 256>>>(out);

    conv1f2_kernel<<<4096, 256, SMEM_C1>>>(out, abi, w1, b1);
    stats_g1_kernel<<<256 * 32, 256>>>();
    finalize_kernel<<<1, 256>>>(1, gm1, be1, 1.0 / 262144.0);

    conv2f2_kernel<<<8192, 128, SMEM_C2K>>>(w2, b2);
    stats_g2_kernel<<<256 * 32, 256>>>();
    finalize_kernel<<<1, 256>>>(2, gm2, be2, 1.0 / 262144.0);

    conv3f2_kernel<<<4096, 128, SMEM_C3>>>(w3, b3);
    stats_g3_kernel<<<128 * 32, 256>>>();
    finalize_kernel<<<1, 256>>>(3, gm3, be3, 1.0 / 262144.0);

    scatter_kernel<<<4096, 256>>>(abi, out);
}